// round 11
// baseline (speedup 1.0000x reference)
#include <cuda_runtime.h>
#include <cstdint>

// ---------------------------------------------------------------------------
// QuantumAttention: B=4, S=1024, E=1024, H=16, HD=64
// out  = [B,S,E]           -> d_out[0 .. 4194304)
// probs= [B,H,S,S] (mixed) -> d_out[4194304 .. 71303168)
// Round 10: eliminate g_E. scores_lite (rowsums only) + mixctx_rc (recompute
// S on tensor cores, mix, write probs once, P@V). K/V served from L2.
// ---------------------------------------------------------------------------

#define Bc 4
#define Sc 1024
#define Ec 1024
#define Hc 16
#define HDc 64
#define Mc (Bc * Sc)           // 4096
#define OUT_OFF (Bc * Sc * Ec) // 4194304

__device__ float g_Wq_eff[Ec * Ec];
__device__ float g_Wk_eff[Ec * Ec];
__device__ float g_bq_eff[Ec];
__device__ float g_bk_eff[Ec];
__device__ float g_Q[Bc * Hc * Sc * HDc];
__device__ float g_K[Bc * Hc * Sc * HDc];
__device__ float g_V[Bc * Hc * Sc * HDc];
__device__ float g_ctx[Bc * Hc * Sc * HDc];
__device__ float g_rowsum[Bc * Hc * Sc];
__device__ int   g_partner[Hc];
__device__ float g_pw[Hc];
__device__ int   g_pairA[Hc / 2];
__device__ int   g_pairB[Hc / 2];

// ---------------------------------------------------------------------------
__device__ __forceinline__ uint32_t f2tf32(float x) {
    uint32_t r;
    asm("cvt.rna.tf32.f32 %0, %1;" : "=r"(r) : "f"(x));
    return r;
}

__device__ __forceinline__ void mma_tf32(float* c, const uint32_t* a,
                                         uint32_t b0, uint32_t b1) {
    asm volatile(
        "mma.sync.aligned.m16n8k8.row.col.f32.tf32.tf32.f32 "
        "{%0,%1,%2,%3}, {%4,%5,%6,%7}, {%8,%9}, {%0,%1,%2,%3};\n"
        : "+f"(c[0]), "+f"(c[1]), "+f"(c[2]), "+f"(c[3])
        : "r"(a[0]), "r"(a[1]), "r"(a[2]), "r"(a[3]), "r"(b0), "r"(b1));
}

// ---------------------------------------------------------------------------
__global__ void init_misc_kernel(const float* __restrict__ ent,
                                 const float* __restrict__ had,
                                 const float* __restrict__ phase,
                                 const float* __restrict__ bq,
                                 const float* __restrict__ bk) {
    int t = threadIdx.x;
    if (t < Hc) {
        int p = t; float w = 0.f;
        for (int h = 0; h < Hc; h++) {
            if (h != t && ent[h * Hc + t] != 0.f) { p = h; w = ent[h * Hc + t]; }
        }
        g_partner[t] = p;
        g_pw[t] = w;
    }
    __syncthreads();
    if (t == 0) {
        int c = 0;
        for (int g = 0; g < Hc; g++) {
            int p = g_partner[g];
            if (p >= g) { g_pairA[c] = g; g_pairB[c] = p; c++; }
        }
    }
    for (int j = t; j < Ec; j += blockDim.x) {
        int h = j >> 6, e = j & 63;
        float aq = 0.f, ak = 0.f;
        for (int d = 0; d < HDc; d++) {
            float hv = had[d * HDc + e];
            aq += hv * bq[h * HDc + d];
            ak += hv * bk[h * HDc + d];
        }
        float c = cosf(phase[j]);
        g_bq_eff[j] = c * aq;
        g_bk_eff[j] = c * ak;
    }
}

__global__ void zero_rowsum_kernel() {
    int i = blockIdx.x * blockDim.x + threadIdx.x;
    if (i < Bc * Hc * Sc) g_rowsum[i] = 0.f;
}

// ---------------------------------------------------------------------------
// Merged weight transform (z = 0: Wq, z = 1: Wk). grid: (16, 16, 2)
// ---------------------------------------------------------------------------
__global__ __launch_bounds__(256) void wtrans_kernel(const float* __restrict__ Wq,
                                                     const float* __restrict__ Wk,
                                                     const float* __restrict__ had,
                                                     const float* __restrict__ phase) {
    const int which = blockIdx.z;
    const float* W = which ? Wk : Wq;
    float* Weff = which ? g_Wk_eff : g_Wq_eff;
    __shared__ float sH[HDc * 65];
    __shared__ float sW[HDc][68];
    __shared__ float sc[HDc];
    const int h = blockIdx.x;
    const int i0 = blockIdx.y * 64;
    const int t = threadIdx.x;
    for (int j = t; j < HDc * HDc; j += 256) {
        int d = j >> 6, e = j & 63;
        sH[d * 65 + e] = had[j];
    }
    if (t < HDc) sc[t] = cosf(phase[h * HDc + t]);
#pragma unroll
    for (int i = 0; i < 4; i++) {
        int idx = i * 256 + t;
        int d = idx >> 4, q = (idx & 15) * 4;
        *(float4*)&sW[d][q] = *(const float4*)&W[(h * HDc + d) * Ec + i0 + q];
    }
    __syncthreads();

    const int tx = t & 15;
    const int ty = t >> 4;
    float acc[4][4];
#pragma unroll
    for (int a = 0; a < 4; a++)
#pragma unroll
        for (int b = 0; b < 4; b++) acc[a][b] = 0.f;

#pragma unroll 8
    for (int d = 0; d < HDc; d++) {
        float4 w = *(const float4*)&sW[d][tx * 4];
#pragma unroll
        for (int ee = 0; ee < 4; ee++) {
            float hv = sH[d * 65 + ty * 4 + ee];
            acc[ee][0] += hv * w.x;
            acc[ee][1] += hv * w.y;
            acc[ee][2] += hv * w.z;
            acc[ee][3] += hv * w.w;
        }
    }
#pragma unroll
    for (int ee = 0; ee < 4; ee++) {
        int e = ty * 4 + ee;
        float s = sc[e];
        float4 o = make_float4(s * acc[ee][0], s * acc[ee][1],
                               s * acc[ee][2], s * acc[ee][3]);
        *(float4*)&Weff[(h * HDc + e) * Ec + i0 + tx * 4] = o;
    }
}

// ---------------------------------------------------------------------------
// GEMM inner tile: [row][k] layout, stride 68 words (R9, proven).
// ---------------------------------------------------------------------------
#define GEMM_MMA_TILE(As, Bs, acc, wm, wn, gid, tig, NKS)                     \
    _Pragma("unroll")                                                         \
    for (int ks = 0; ks < NKS; ks++) {                                        \
        int kb = ks * 8;                                                      \
        uint32_t a[2][4];                                                     \
        _Pragma("unroll")                                                     \
        for (int mi = 0; mi < 2; mi++) {                                      \
            int r = (wm) + mi * 16 + (gid);                                   \
            a[mi][0] = (As)[r][kb + (tig)];                                   \
            a[mi][1] = (As)[r + 8][kb + (tig)];                               \
            a[mi][2] = (As)[r][kb + (tig) + 4];                               \
            a[mi][3] = (As)[r + 8][kb + (tig) + 4];                           \
        }                                                                     \
        _Pragma("unroll")                                                     \
        for (int ni = 0; ni < 8; ni++) {                                      \
            int c = (wn) + ni * 8 + (gid);                                    \
            uint32_t b0 = (Bs)[c][kb + (tig)];                                \
            uint32_t b1 = (Bs)[c][kb + (tig) + 4];                            \
            mma_tf32(acc[0][ni], a[0], b0, b1);                               \
            mma_tf32(acc[1][ni], a[1], b0, b1);                               \
        }                                                                     \
    }

#define GEMM_FILL4(Sm, row, kq, v)                                            \
    do {                                                                      \
        uint4 _u = make_uint4(f2tf32((v).x), f2tf32((v).y),                   \
                              f2tf32((v).z), f2tf32((v).w));                  \
        *(uint4*)&(Sm)[row][kq] = _u;                                         \
    } while (0)

// ---------------------------------------------------------------------------
// Merged TF32 projection GEMM (z selects q/k/v). grid: (8, 32, 3)
// ---------------------------------------------------------------------------
__global__ __launch_bounds__(256) void gemm_tf32_proj(
    const float* __restrict__ Aq, const float* __restrict__ Ak,
    const float* __restrict__ Av, const float* __restrict__ Wv,
    const float* __restrict__ bv) {
    const int which = blockIdx.z;
    const float* A    = (which == 0) ? Aq : (which == 1) ? Ak : Av;
    const float* W    = (which == 0) ? g_Wq_eff : (which == 1) ? g_Wk_eff : Wv;
    const float* bias = (which == 0) ? g_bq_eff : (which == 1) ? g_bk_eff : bv;
    float* Out        = (which == 0) ? g_Q : (which == 1) ? g_K : g_V;

    __shared__ uint32_t As[128][68];
    __shared__ uint32_t Bs[128][68];
    const int t = threadIdx.x;
    const int lane = t & 31, warp = t >> 5;
    const int gid = lane >> 2, tig = lane & 3;
    const int wm = (warp & 3) * 32, wn = (warp >> 2) * 64;
    const int m0 = blockIdx.y * 128, n0 = blockIdx.x * 128;

    float acc[2][8][4];
#pragma unroll
    for (int mi = 0; mi < 2; mi++)
#pragma unroll
        for (int ni = 0; ni < 8; ni++)
#pragma unroll
            for (int j = 0; j < 4; j++) acc[mi][ni][j] = 0.f;

    for (int k0 = 0; k0 < Ec; k0 += 64) {
#pragma unroll
        for (int i = 0; i < 8; i++) {
            int idx = i * 256 + t;
            int row = idx >> 4, kq = (idx & 15) * 4;
            float4 va = *(const float4*)&A[(m0 + row) * Ec + k0 + kq];
            GEMM_FILL4(As, row, kq, va);
            float4 vb = *(const float4*)&W[(n0 + row) * Ec + k0 + kq];
            GEMM_FILL4(Bs, row, kq, vb);
        }
        __syncthreads();
        GEMM_MMA_TILE(As, Bs, acc, wm, wn, gid, tig, 8)
        __syncthreads();
    }

#pragma unroll
    for (int mi = 0; mi < 2; mi++) {
        int r0 = m0 + wm + mi * 16 + gid;
#pragma unroll
        for (int ni = 0; ni < 8; ni++) {
            int col = n0 + wn + ni * 8 + tig * 2;
            float bb0 = bias[col], bb1 = bias[col + 1];
            int h = col >> 6, d = col & 63;
            {
                int m = r0, b = m >> 10, s = m & 1023;
                *(float2*)&Out[((b * Hc + h) * Sc + s) * HDc + d] =
                    make_float2(acc[mi][ni][0] + bb0, acc[mi][ni][1] + bb1);
            }
            {
                int m = r0 + 8, b = m >> 10, s = m & 1023;
                *(float2*)&Out[((b * Hc + h) * Sc + s) * HDc + d] =
                    make_float2(acc[mi][ni][2] + bb0, acc[mi][ni][3] + bb1);
            }
        }
    }
}

// ---------------------------------------------------------------------------
// scores_lite: rowsums of exp(QK^T/8) only — NO E store. grid: (8, 8, 64)
// ---------------------------------------------------------------------------
__global__ __launch_bounds__(256) void scores_lite_kernel() {
    __shared__ uint32_t As[128][68];
    __shared__ uint32_t Bs[128][68];
    __shared__ float rs[128];
    const int t = threadIdx.x;
    const int lane = t & 31, warp = t >> 5;
    const int gid = lane >> 2, tig = lane & 3;
    const int wm = (warp & 3) * 32, wn = (warp >> 2) * 64;
    const int bh = blockIdx.z;
    const int m0 = blockIdx.y * 128, n0 = blockIdx.x * 128;
    const float* Qb = g_Q + (size_t)bh * Sc * HDc;
    const float* Kb = g_K + (size_t)bh * Sc * HDc;

    float acc[2][8][4];
#pragma unroll
    for (int mi = 0; mi < 2; mi++)
#pragma unroll
        for (int ni = 0; ni < 8; ni++)
#pragma unroll
            for (int j = 0; j < 4; j++) acc[mi][ni][j] = 0.f;

#pragma unroll
    for (int i = 0; i < 8; i++) {
        int idx = i * 256 + t;
        int row = idx >> 4, kq = (idx & 15) * 4;
        float4 va = *(const float4*)&Qb[(m0 + row) * HDc + kq];
        GEMM_FILL4(As, row, kq, va);
        float4 vb = *(const float4*)&Kb[(n0 + row) * HDc + kq];
        GEMM_FILL4(Bs, row, kq, vb);
    }
    __syncthreads();
    GEMM_MMA_TILE(As, Bs, acc, wm, wn, gid, tig, 8)

    if (t < 128) rs[t] = 0.f;
    __syncthreads();

#pragma unroll
    for (int mi = 0; mi < 2; mi++) {
        int r0 = wm + mi * 16 + gid;
        float rsum0 = 0.f, rsum1 = 0.f;
#pragma unroll
        for (int ni = 0; ni < 8; ni++) {
            rsum0 += __expf(acc[mi][ni][0] * 0.125f) + __expf(acc[mi][ni][1] * 0.125f);
            rsum1 += __expf(acc[mi][ni][2] * 0.125f) + __expf(acc[mi][ni][3] * 0.125f);
        }
        atomicAdd(&rs[r0], rsum0);
        atomicAdd(&rs[r0 + 8], rsum1);
    }
    __syncthreads();
    if (t < 128) atomicAdd(&g_rowsum[bh * Sc + m0 + t], rs[t]);
}

// ---------------------------------------------------------------------------
// mixctx_rc: recompute S, exp, mix pair, write probs (final), P@V -> ctx.
// CTA = (b, pair, 32 q rows), 256 thr. Warps 0-3 head g, 4-7 head p; within a
// head, warp w4: rows (w4&1)*16, S-keys/PV-cols (w4>>1)*32.
// Dynamic smem 104960 B -> 2 CTAs/SM. grid: (32, 32).
// smem words: sQ[2][32][68] @0, sK[2][64][68] @4352, sV[2][64][68] @13056,
//             sP[2][32][68] @21760 (E then tf32 P), iv[4][32] @26112.
// ---------------------------------------------------------------------------
#define MCTX_SMEM_BYTES ((26112 + 128) * 4)

__global__ __launch_bounds__(256) void mixctx_rc_kernel(float* __restrict__ Pout) {
    extern __shared__ uint32_t sm[];
    uint32_t* const sQ = sm;
    uint32_t* const sK = sm + 4352;
    uint32_t* const sV = sm + 13056;
    uint32_t* const sP = sm + 21760;
    float* const iv = (float*)(sm + 26112);

    const int t = threadIdx.x;
    const int lane = t & 31, warp = t >> 5;
    const int gid = lane >> 2, tig = lane & 3;
    const int hw = warp >> 2;
    const int w4 = warp & 3;
    const int r0 = (w4 & 1) * 16;
    const int c0 = (w4 >> 1) * 32;
    const int bp = blockIdx.y;
    const int b = bp >> 3, pr = bp & 7;
    const int g = g_pairA[pr], p = g_pairB[pr];
    const int q0 = blockIdx.x * 32;

    if (t < 32) {
        float rg = g_rowsum[(b * Hc + g) * Sc + q0 + t];
        float rp = g_rowsum[(b * Hc + p) * Sc + q0 + t];
        float w = g_pw[g];
        iv[t]      = 1.f / rg;   // Eg -> probs_g
        iv[32 + t] = 1.f / rp;   // Ep -> probs_p
        iv[64 + t] = w / rp;     // Ep -> probs_g
        iv[96 + t] = w / rg;     // Eg -> probs_p
    }

    const float* QB[2] = { g_Q + (size_t)(b * Hc + g) * Sc * HDc,
                           g_Q + (size_t)(b * Hc + p) * Sc * HDc };
    const float* KB[2] = { g_K + (size_t)(b * Hc + g) * Sc * HDc,
                           g_K + (size_t)(b * Hc + p) * Sc * HDc };
    const float* VB[2] = { g_V + (size_t)(b * Hc + g) * Sc * HDc,
                           g_V + (size_t)(b * Hc + p) * Sc * HDc };
    float* PB[2] = { Pout + (size_t)(b * Hc + g) * Sc * Sc,
                     Pout + (size_t)(b * Hc + p) * Sc * Sc };

    // Q tiles resident: 2 x 32 x 64 -> 4 float4 per thread
#pragma unroll
    for (int i = 0; i < 4; i++) {
        int idx = i * 256 + t;
        int head = idx >> 9, rem = idx & 511;
        int row = rem >> 4, d0 = (rem & 15) * 4;
        float4 v = *(const float4*)&QB[head][(size_t)(q0 + row) * HDc + d0];
        uint4 u = make_uint4(f2tf32(v.x), f2tf32(v.y), f2tf32(v.z), f2tf32(v.w));
        *(uint4*)&sQ[head * 2176 + row * 68 + d0] = u;
    }
    __syncthreads();

    float accC[4][4];
#pragma unroll
    for (int ni = 0; ni < 4; ni++)
#pragma unroll
        for (int j = 0; j < 4; j++) accC[ni][j] = 0.f;

    const uint32_t* Qh = sQ + hw * 2176;
    const uint32_t* Kh = sK + hw * 4352;
    const uint32_t* Vh = sV + hw * 4352;
    uint32_t* Eh = sP + hw * 2176;

    for (int kt = 0; kt < Sc; kt += 64) {
        // fill K, V chunks: 8 float4 per thread each
#pragma unroll
        for (int i = 0; i < 8; i++) {
            int idx = i * 256 + t;
            int head = idx >> 10, rem = idx & 1023;
            int key = rem >> 4, d0 = (rem & 15) * 4;
            float4 vk = *(const float4*)&KB[head][(size_t)(kt + key) * HDc + d0];
            uint4 uk = make_uint4(f2tf32(vk.x), f2tf32(vk.y), f2tf32(vk.z), f2tf32(vk.w));
            *(uint4*)&sK[head * 4352 + key * 68 + d0] = uk;
            float4 vv = *(const float4*)&VB[head][(size_t)(kt + key) * HDc + d0];
            uint4 uv = make_uint4(f2tf32(vv.x), f2tf32(vv.y), f2tf32(vv.z), f2tf32(vv.w));
            *(uint4*)&sV[head * 4352 + key * 68 + d0] = uv;
        }
        __syncthreads();

        // S = Q K^T (rows r0..+16, keys c0..+32), exp -> Eh
        {
            float accS[4][4];
#pragma unroll
            for (int ni = 0; ni < 4; ni++)
#pragma unroll
                for (int j = 0; j < 4; j++) accS[ni][j] = 0.f;
#pragma unroll
            for (int ks = 0; ks < 8; ks++) {
                int kb = ks * 8;
                uint32_t a[4];
                a[0] = Qh[(r0 + gid) * 68 + kb + tig];
                a[1] = Qh[(r0 + gid + 8) * 68 + kb + tig];
                a[2] = Qh[(r0 + gid) * 68 + kb + tig + 4];
                a[3] = Qh[(r0 + gid + 8) * 68 + kb + tig + 4];
#pragma unroll
                for (int ni = 0; ni < 4; ni++) {
                    int c = c0 + ni * 8 + gid;
                    uint32_t b0 = Kh[c * 68 + kb + tig];
                    uint32_t b1 = Kh[c * 68 + kb + tig + 4];
                    mma_tf32(accS[ni], a, b0, b1);
                }
            }
#pragma unroll
            for (int ni = 0; ni < 4; ni++) {
                int col = c0 + ni * 8 + tig * 2;
                Eh[(r0 + gid) * 68 + col]     = __float_as_uint(__expf(accS[ni][0] * 0.125f));
                Eh[(r0 + gid) * 68 + col + 1] = __float_as_uint(__expf(accS[ni][1] * 0.125f));
                Eh[(r0 + gid + 8) * 68 + col]     = __float_as_uint(__expf(accS[ni][2] * 0.125f));
                Eh[(r0 + gid + 8) * 68 + col + 1] = __float_as_uint(__expf(accS[ni][3] * 0.125f));
            }
        }
        __syncthreads();

        // mix + probs write + tf32 staging (in place). 2 float4 per thread.
#pragma unroll
        for (int j = 0; j < 2; j++) {
            int idx = j * 256 + t;
            int row = idx >> 4, c = (idx & 15) * 4;
            float4 eg = *(float4*)&sP[row * 68 + c];
            float4 ep = *(float4*)&sP[2176 + row * 68 + c];
            float i0 = iv[row], i1 = iv[32 + row];
            float i2 = iv[64 + row], i3 = iv[96 + row];
            float4 pg = make_float4(eg.x * i0 + ep.x * i2, eg.y * i0 + ep.y * i2,
                                    eg.z * i0 + ep.z * i2, eg.w * i0 + ep.w * i2);
            float4 pp = make_float4(ep.x * i1 + eg.x * i3, ep.y * i1 + eg.y * i3,
                                    ep.z * i1 + eg.z * i3, ep.w * i1 + eg.w * i3);
            *(float4*)&PB[0][(size_t)(q0 + row) * Sc + kt + c] = pg;
            *(float4*)&PB[1][(size_t)(q0 + row) * Sc + kt + c] = pp;
            uint4 ug = make_uint4(f2tf32(pg.x), f2tf32(pg.y), f2tf32(pg.z), f2tf32(pg.w));
            uint4 up = make_uint4(f2tf32(pp.x), f2tf32(pp.y), f2tf32(pp.z), f2tf32(pp.w));
            *(uint4*)&sP[row * 68 + c] = ug;
            *(uint4*)&sP[2176 + row * 68 + c] = up;
        }
        __syncthreads();

        // ctx += P V (rows r0..+16, d cols c0..+32, k = 64 keys)
#pragma unroll
        for (int ks = 0; ks < 8; ks++) {
            int kb = ks * 8;
            uint32_t a[4];
            a[0] = Eh[(r0 + gid) * 68 + kb + tig];
            a[1] = Eh[(r0 + gid + 8) * 68 + kb + tig];
            a[2] = Eh[(r0 + gid) * 68 + kb + tig + 4];
            a[3] = Eh[(r0 + gid + 8) * 68 + kb + tig + 4];
#pragma unroll
            for (int ni = 0; ni < 4; ni++) {
                int d = c0 + ni * 8 + gid;
                uint32_t b0 = Vh[(kb + tig) * 68 + d];
                uint32_t b1 = Vh[(kb + tig + 4) * 68 + d];
                mma_tf32(accC[ni], a, b0, b1);
            }
        }
        __syncthreads();   // sK/sV/sP reused next chunk
    }

    // epilogue: ctx
    const int h = hw ? p : g;
    float* Cb = g_ctx + ((size_t)(b * Hc + h) * Sc + q0) * HDc;
#pragma unroll
    for (int ni = 0; ni < 4; ni++) {
        int d = c0 + ni * 8 + tig * 2;
        *(float2*)&Cb[(r0 + gid) * HDc + d] = make_float2(accC[ni][0], accC[ni][1]);
        *(float2*)&Cb[(r0 + gid + 8) * HDc + d] = make_float2(accC[ni][2], accC[ni][3]);
    }
}

// ---------------------------------------------------------------------------
// TF32 output projection: out[4096,1024] = ctx_flat @ Wo^T + bo. grid: (8, 32)
// ---------------------------------------------------------------------------
__global__ __launch_bounds__(256) void gemm_tf32_out(
    const float* __restrict__ W, const float* __restrict__ bias,
    float* __restrict__ Out) {
    __shared__ uint32_t As[128][68];
    __shared__ uint32_t Bs[128][68];
    const int t = threadIdx.x;
    const int lane = t & 31, warp = t >> 5;
    const int gid = lane >> 2, tig = lane & 3;
    const int wm = (warp & 3) * 32, wn = (warp >> 2) * 64;
    const int m0 = blockIdx.y * 128, n0 = blockIdx.x * 128;

    float acc[2][8][4];
#pragma unroll
    for (int mi = 0; mi < 2; mi++)
#pragma unroll
        for (int ni = 0; ni < 8; ni++)
#pragma unroll
            for (int j = 0; j < 4; j++) acc[mi][ni][j] = 0.f;

    for (int k0 = 0; k0 < Ec; k0 += 64) {
#pragma unroll
        for (int i = 0; i < 8; i++) {
            int idx = i * 256 + t;
            int row = idx >> 4, kq = (idx & 15) * 4;
            int k = k0 + kq;
            int m = m0 + row, b = m >> 10, s = m & 1023;
            float4 va = *(const float4*)&g_ctx[((b * Hc + (k >> 6)) * Sc + s) * HDc + (k & 63)];
            GEMM_FILL4(As, row, kq, va);
            float4 vb = *(const float4*)&W[(n0 + row) * Ec + k];
            GEMM_FILL4(Bs, row, kq, vb);
        }
        __syncthreads();
        GEMM_MMA_TILE(As, Bs, acc, wm, wn, gid, tig, 8)
        __syncthreads();
    }

#pragma unroll
    for (int mi = 0; mi < 2; mi++) {
        int r0 = m0 + wm + mi * 16 + gid;
#pragma unroll
        for (int ni = 0; ni < 8; ni++) {
            int col = n0 + wn + ni * 8 + tig * 2;
            float bb0 = bias[col], bb1 = bias[col + 1];
            *(float2*)&Out[r0 * Ec + col] =
                make_float2(acc[mi][ni][0] + bb0, acc[mi][ni][1] + bb1);
            *(float2*)&Out[(r0 + 8) * Ec + col] =
                make_float2(acc[mi][ni][2] + bb0, acc[mi][ni][3] + bb1);
        }
    }
}

// ---------------------------------------------------------------------------
extern "C" void kernel_launch(void* const* d_in, const int* in_sizes, int n_in,
                              void* d_out, int out_size) {
    const float* query    = (const float*)d_in[0];
    const float* key      = (const float*)d_in[1];
    const float* value    = (const float*)d_in[2];
    const float* Wq       = (const float*)d_in[3];
    const float* bq       = (const float*)d_in[4];
    const float* Wk       = (const float*)d_in[5];
    const float* bk       = (const float*)d_in[6];
    const float* Wv       = (const float*)d_in[7];
    const float* bv       = (const float*)d_in[8];
    const float* Wo       = (const float*)d_in[9];
    const float* bo       = (const float*)d_in[10];
    const float* phase    = (const float*)d_in[11];
    const float* hadamard = (const float*)d_in[12];
    const float* ent      = (const float*)d_in[13];

    float* out   = (float*)d_out;
    float* probs = out + OUT_OFF;

    cudaFuncSetAttribute(mixctx_rc_kernel,
                         cudaFuncAttributeMaxDynamicSharedMemorySize,
                         MCTX_SMEM_BYTES);

    init_misc_kernel<<<1, 256>>>(ent, hadamard, phase, bq, bk);
    zero_rowsum_kernel<<<(Bc * Hc * Sc) / 256, 256>>>();
    wtrans_kernel<<<dim3(Hc, 16, 2), 256>>>(Wq, Wk, hadamard, phase);

    gemm_tf32_proj<<<dim3(Ec / 128, Mc / 128, 3), 256>>>(query, key, value, Wv, bv);

    scores_lite_kernel<<<dim3(Sc / 128, Sc / 128, Bc * Hc), 256>>>();
    mixctx_rc_kernel<<<dim3(Sc / 32, Bc * 8), 256, MCTX_SMEM_BYTES>>>(probs);
    gemm_tf32_out<<<dim3(Ec / 128, Mc / 128), 256>>>(Wo, bo, out);
}